// round 1
// baseline (speedup 1.0000x reference)
#include <cuda_runtime.h>
#include <cstdint>

// Problem constants
#define ROWS   65536        // B*n = 8192*8
#define NE     1024         // codebook size
#define ED     64           // codebook dim
#define CHUNK  64           // codebook entries staged per iteration
#define RPB    64           // rows per block
#define TR     8            // rows per warp (8 warps * 8 = 64)
#define TE     2            // entries per lane per chunk (CHUNK/32)

// Output layout (tuple flattened, all float32)
#define OFF_LOSS  0
#define OFF_L1    1
#define OFF_L2    2
#define OFF_ZQST  3
#define OFF_ZOUT  4194307
#define OFF_PERP  8388611
#define OFF_OH    8388612
#define OFF_IDX   75497476

// Scratch (no cudaMalloc allowed)
__device__ int    g_idx[ROWS];
__device__ int    g_hist[NE];
__device__ double g_loss;
__device__ float  g_wsum[NE];

__device__ __forceinline__ void ffma2(unsigned long long &acc,
                                      unsigned long long a,
                                      unsigned long long b) {
    asm("fma.rn.f32x2 %0, %1, %2, %0;" : "+l"(acc) : "l"(a), "l"(b));
}

__device__ __forceinline__ float2 unpack2(unsigned long long v) {
    float2 r;
    asm("mov.b64 {%0, %1}, %2;" : "=f"(r.x), "=f"(r.y) : "l"(v));
    return r;
}

// ---------------------------------------------------------------------------
// prep: per-entry ||w||^2, zero histogram + loss accumulator
// ---------------------------------------------------------------------------
__global__ void vq_prep(const float* __restrict__ w) {
    int e = blockIdx.x, lane = threadIdx.x;
    const float* wr = w + e * ED;
    float a = wr[lane], b = wr[lane + 32];
    float s = a * a + b * b;
    #pragma unroll
    for (int o = 16; o; o >>= 1) s += __shfl_down_sync(0xffffffffu, s, o);
    if (lane == 0) {
        g_wsum[e] = s;
        g_hist[e] = 0;
        if (e == 0) g_loss = 0.0;
    }
}

// ---------------------------------------------------------------------------
// zero fill for one-hot region (268 MB)
// ---------------------------------------------------------------------------
__global__ void vq_zero(float4* __restrict__ dst, int n) {
    int i = blockIdx.x * blockDim.x + threadIdx.x;
    int stride = gridDim.x * blockDim.x;
    float4 z4 = make_float4(0.f, 0.f, 0.f, 0.f);
    for (; i < n; i += stride) dst[i] = z4;
}

// ---------------------------------------------------------------------------
// main kernel: fused distance-GEMM + row argmin + z_q epilogue
// Each block: 64 rows. Each warp: 8 rows. Each lane: 2 codebook entries/chunk.
// Scores computed exactly as reference: (||z||^2 + ||w||^2) - 2*dot, fp32.
// ---------------------------------------------------------------------------
__global__ __launch_bounds__(256) void vq_argmin(
    const float* __restrict__ z, const float* __restrict__ w,
    float* __restrict__ out)
{
    __shared__ float  zs[RPB * ED];       // 16 KB: z tile (row-major)
    __shared__ float2 wp[32 * CHUNK];     // 16 KB: w chunk, [dpair][entry] swizzled
    __shared__ float  zsum[RPB];

    const int tid = threadIdx.x, lane = tid & 31, warp = tid >> 5;
    const int rowBase = blockIdx.x * RPB;
    const int myRow0 = warp * TR;

    // stage z tile (coalesced float4)
    {
        const float4* zg = (const float4*)(z + (size_t)rowBase * ED);
        float4* zt = (float4*)zs;
        #pragma unroll
        for (int i = tid; i < RPB * ED / 4; i += 256) zt[i] = zg[i];
    }
    __syncthreads();
    if (tid < RPB) {
        const float* zr = zs + tid * ED;
        float s = 0.f;
        #pragma unroll
        for (int d = 0; d < ED; d++) s += zr[d] * zr[d];
        zsum[tid] = s;
    }

    float best[TR]; int bidx[TR];
    #pragma unroll
    for (int r = 0; r < TR; r++) { best[r] = 3.402823e38f; bidx[r] = 0x7fffffff; }

    const float2* zs2 = (const float2*)zs;

    for (int c = 0; c < NE; c += CHUNK) {
        __syncthreads();   // protect wp reuse + order zsum writes
        // stage w chunk as [dpair][entry] with xor-swizzle (conflict-free LDS)
        {
            const float2* wg = (const float2*)(w + (size_t)c * ED);
            #pragma unroll
            for (int i = tid; i < CHUNK * 32; i += 256) {
                int e = i >> 5, dp = i & 31;
                int col = (e & ~31) | ((e & 31) ^ dp);
                wp[dp * CHUNK + col] = wg[i];
            }
        }
        __syncthreads();

        unsigned long long acc[TR][TE];
        #pragma unroll
        for (int r = 0; r < TR; r++)
            #pragma unroll
            for (int j = 0; j < TE; j++) acc[r][j] = 0ull;

        #pragma unroll 8
        for (int dp = 0; dp < 32; dp++) {
            unsigned long long zv[TR], wv[TE];
            #pragma unroll
            for (int r = 0; r < TR; r++)
                zv[r] = *(const unsigned long long*)&zs2[(myRow0 + r) * 32 + dp];
            #pragma unroll
            for (int j = 0; j < TE; j++) {
                int col = (j << 5) | (lane ^ dp);
                wv[j] = *(const unsigned long long*)&wp[dp * CHUNK + col];
            }
            #pragma unroll
            for (int r = 0; r < TR; r++)
                #pragma unroll
                for (int j = 0; j < TE; j++)
                    ffma2(acc[r][j], zv[r], wv[j]);
        }

        #pragma unroll
        for (int r = 0; r < TR; r++) {
            float zsr = zsum[myRow0 + r];
            #pragma unroll
            for (int j = 0; j < TE; j++) {
                float2 a = unpack2(acc[r][j]);
                float dot = a.x + a.y;
                int e = c + (j << 5) + lane;
                float t = zsr + g_wsum[e];
                float s = t - 2.0f * dot;      // matches reference fp32 ordering
                if (s < best[r] || (s == best[r] && e < bidx[r])) {
                    best[r] = s; bidx[r] = e;
                }
            }
        }
    }

    // per-row warp reduction + epilogue
    double dacc = 0.0;
    #pragma unroll
    for (int r = 0; r < TR; r++) {
        float v = best[r]; int id = bidx[r];
        #pragma unroll
        for (int o = 16; o; o >>= 1) {
            float v2 = __shfl_down_sync(0xffffffffu, v, o);
            int   i2 = __shfl_down_sync(0xffffffffu, id, o);
            if (v2 < v || (v2 == v && i2 < id)) { v = v2; id = i2; }
        }
        id = __shfl_sync(0xffffffffu, id, 0);

        int grow = rowBase + myRow0 + r;
        const float* wrow = w + (size_t)id * ED;
        float dsq = 0.f;
        #pragma unroll
        for (int d = lane; d < ED; d += 32) {
            float zq = wrow[d];                  // z_q = exact codebook row
            float zr = zs[(myRow0 + r) * ED + d];
            float df = zq - zr;
            float st = zr + df;                  // straight-through fp32 replay
            out[OFF_ZQST + (size_t)grow * ED + d] = st;
            out[OFF_ZOUT + (size_t)grow * ED + d] = st;
            dsq += df * df;
        }
        #pragma unroll
        for (int o = 16; o; o >>= 1) dsq += __shfl_down_sync(0xffffffffu, dsq, o);
        if (lane == 0) {
            g_idx[grow] = id;
            atomicAdd(&g_hist[id], 1);
            out[OFF_IDX + grow] = (float)id;
            dacc += (double)dsq;
        }
    }
    if (lane == 0 && dacc != 0.0) atomicAdd(&g_loss, dacc);
}

// ---------------------------------------------------------------------------
// scatter ones into the one-hot matrix
// ---------------------------------------------------------------------------
__global__ void vq_scatter(float* __restrict__ oh) {
    int i = blockIdx.x * blockDim.x + threadIdx.x;
    if (i < ROWS) oh[(size_t)i * NE + g_idx[i]] = 1.0f;
}

// ---------------------------------------------------------------------------
// finalize: losses + perplexity scalars
// ---------------------------------------------------------------------------
__global__ void vq_finalize(float* __restrict__ out) {
    __shared__ float red[1024];
    int t = threadIdx.x;
    float p = (float)g_hist[t] / 65536.0f;
    red[t] = p * logf(p + 1e-10f);
    __syncthreads();
    #pragma unroll
    for (int s = 512; s; s >>= 1) {
        if (t < s) red[t] += red[t + s];
        __syncthreads();
    }
    if (t == 0) {
        out[OFF_PERP] = expf(-red[0]);
        float l1 = (float)(g_loss / 4194304.0);
        out[OFF_L1] = l1;
        out[OFF_L2] = l1;                 // loss2 == loss1 numerically
        out[OFF_LOSS] = l1 + 0.25f * l1;  // GAMMA*l1 + BETA*l2
    }
}

// ---------------------------------------------------------------------------
extern "C" void kernel_launch(void* const* d_in, const int* in_sizes, int n_in,
                              void* d_out, int out_size)
{
    const float* z = (const float*)d_in[0];   // (8192, 512)
    const float* w = (const float*)d_in[1];   // (1024, 64)
    float* out = (float*)d_out;

    vq_prep<<<NE, 32>>>(w);
    vq_zero<<<8192, 256>>>((float4*)(out + OFF_OH), (NE * ROWS) / 4);
    vq_argmin<<<ROWS / RPB, 256>>>(z, w, out);
    vq_scatter<<<(ROWS + 255) / 256, 256>>>(out + OFF_OH);
    vq_finalize<<<1, 1024>>>(out);
}